// round 4
// baseline (speedup 1.0000x reference)
#include <cuda_runtime.h>
#include <math.h>

#define NN   50000
#define EE   800000
#define DIN  127
#define DD   128
#define NCLS 40
#define EPSV 1e-8f

#define GBM  64      // gemm block rows
#define LDP  68      // smem panel leading dim (floats)
#define LDD  132     // D staging leading dim

// Scratch (__device__ globals: allocation-free rule)
__device__ float g_A[NN * DD];
__device__ float g_B[NN * DD];
__device__ int   g_deg[NN];
__device__ int   g_offs[NN];
__device__ int   g_cursor[NN];
__device__ int2  g_pair[EE];

__device__ __forceinline__ float warpSum(float v) {
#pragma unroll
    for (int o = 16; o; o >>= 1) v += __shfl_xor_sync(0xffffffffu, v, o);
    return v;
}

__device__ __forceinline__ void split_tf32(float x, unsigned& hi, unsigned& lo) {
    unsigned h;
    asm("cvt.rna.tf32.f32 %0, %1;" : "=r"(h) : "f"(x));
    float r = x - __uint_as_float(h);
    unsigned l;
    asm("cvt.rna.tf32.f32 %0, %1;" : "=r"(l) : "f"(r));
    hi = h; lo = l;
}

__device__ __forceinline__ void mma8(float* d, const unsigned* a, const unsigned* b) {
    asm volatile(
        "mma.sync.aligned.m16n8k8.row.col.f32.tf32.tf32.f32 "
        "{%0,%1,%2,%3}, {%4,%5,%6,%7}, {%8,%9}, {%0,%1,%2,%3};"
        : "+f"(d[0]), "+f"(d[1]), "+f"(d[2]), "+f"(d[3])
        : "r"(a[0]), "r"(a[1]), "r"(a[2]), "r"(a[3]), "r"(b[0]), "r"(b[1]));
}

// ---------------------------------------------------------------------------
// Edge binning
// ---------------------------------------------------------------------------
__global__ void count_kernel(const int* __restrict__ er, int* __restrict__ deg) {
    int i = blockIdx.x * blockDim.x + threadIdx.x;
    int stride = gridDim.x * blockDim.x;
    for (int e = i; e < EE; e += stride) atomicAdd(&deg[er[e]], 1);
}

__global__ void scan_kernel(const int* __restrict__ deg, int* __restrict__ offs,
                            int* __restrict__ cursor) {
    __shared__ int sums[1024];
    const int CH = (NN + 1023) / 1024;
    int t = threadIdx.x;
    int base = t * CH;
    int s = 0;
    for (int i = 0; i < CH; i++) {
        int idx = base + i;
        if (idx < NN) s += deg[idx];
    }
    sums[t] = s;
    __syncthreads();
    for (int o = 1; o < 1024; o <<= 1) {
        int v = (t >= o) ? sums[t - o] : 0;
        __syncthreads();
        sums[t] += v;
        __syncthreads();
    }
    int run = (t == 0) ? 0 : sums[t - 1];
    for (int i = 0; i < CH; i++) {
        int idx = base + i;
        if (idx < NN) {
            offs[idx] = run;
            cursor[idx] = run;
            run += deg[idx];
        }
    }
}

__global__ void scatter_kernel(const int* __restrict__ er, const int* __restrict__ ec,
                               const float* __restrict__ ew,
                               int* __restrict__ cursor, int2* __restrict__ pair) {
    int i = blockIdx.x * blockDim.x + threadIdx.x;
    int stride = gridDim.x * blockDim.x;
    for (int e = i; e < EE; e += stride) {
        int r = er[e];
        int pos = atomicAdd(&cursor[r], 1);
        pair[pos] = make_int2(ec[e], __float_as_int(ew[e]));
    }
}

// ---------------------------------------------------------------------------
// expmap0: one warp per node
// ---------------------------------------------------------------------------
__global__ void expmap_kernel(const float* __restrict__ nf, float* __restrict__ out) {
    int lane = threadIdx.x & 31;
    int warp = (blockIdx.x * blockDim.x + threadIdx.x) >> 5;
    if (warp >= NN) return;
    const float* u = nf + (size_t)warp * DIN;
    float v[4];
    float ss = 0.f;
#pragma unroll
    for (int i = 0; i < 4; i++) {
        int j = lane * 4 + i;
        v[i] = (j < DIN) ? u[j] : 0.f;
        ss += v[i] * v[i];
    }
    ss = warpSum(ss);
    float nrm = fmaxf(sqrtf(ss), EPSV);
    float f = sinhf(nrm) / nrm;
    float* o = out + (size_t)warp * DD;
    if (lane == 0) o[0] = coshf(nrm);
#pragma unroll
    for (int i = 0; i < 4; i++) {
        int j = lane * 4 + i;
        if (j < DIN) o[1 + j] = f * v[i];
    }
}

// ---------------------------------------------------------------------------
// GEMM via 3xTF32 mma.sync: H = X @ W^T + b, Lorentz epilogue.
// ---------------------------------------------------------------------------
__global__ void __launch_bounds__(256, 2) gemm_tc(
    const float* __restrict__ X, const float* __restrict__ W,
    const float* __restrict__ bias, const float* __restrict__ logs,
    float* __restrict__ out) {
    extern __shared__ float sm[];
    float* sX = sm;
    float* sW = sm + GBM * LDP;
    float* sD = sm;
    float* rowT = sm + GBM * LDP + 128 * LDP;
    float* rowS = rowT + GBM;

    int tid = threadIdx.x;
    int lane = tid & 31, wid = tid >> 5;
    int g = lane >> 2, t = lane & 3;
    int warpM = wid & 1, warpN = wid >> 1;
    int rowBase = blockIdx.x * GBM;

    float acc[2][4][4];
#pragma unroll
    for (int a = 0; a < 2; a++)
#pragma unroll
        for (int b = 0; b < 4; b++)
#pragma unroll
            for (int c = 0; c < 4; c++) acc[a][b][c] = 0.f;

    for (int kb = 0; kb < DD; kb += 64) {
#pragma unroll
        for (int i = 0; i < 4; i++) {
            int idx = tid + 256 * i;
            int r = idx >> 4, c4 = idx & 15;
            int gr = rowBase + r;
            float4 v = make_float4(0.f, 0.f, 0.f, 0.f);
            if (gr < NN) v = *(const float4*)(X + (size_t)gr * DD + kb + c4 * 4);
            *(float4*)(sX + r * LDP + c4 * 4) = v;
        }
#pragma unroll
        for (int i = 0; i < 8; i++) {
            int idx = tid + 256 * i;
            int r = idx >> 4, c4 = idx & 15;
            float4 v = *(const float4*)(W + (size_t)r * DD + kb + c4 * 4);
            *(float4*)(sW + r * LDP + c4 * 4) = v;
        }
        __syncthreads();

#pragma unroll
        for (int ks = 0; ks < 8; ks++) {
            int k0 = ks * 8;
            unsigned ah[2][4], al[2][4], bh[4][2], bl[4][2];
#pragma unroll
            for (int mf = 0; mf < 2; mf++) {
                int r0 = warpM * 32 + mf * 16 + g;
                split_tf32(sX[r0 * LDP + k0 + t],           ah[mf][0], al[mf][0]);
                split_tf32(sX[(r0 + 8) * LDP + k0 + t],     ah[mf][1], al[mf][1]);
                split_tf32(sX[r0 * LDP + k0 + t + 4],       ah[mf][2], al[mf][2]);
                split_tf32(sX[(r0 + 8) * LDP + k0 + t + 4], ah[mf][3], al[mf][3]);
            }
#pragma unroll
            for (int nf = 0; nf < 4; nf++) {
                int c0 = warpN * 32 + nf * 8 + g;
                split_tf32(sW[c0 * LDP + k0 + t],     bh[nf][0], bl[nf][0]);
                split_tf32(sW[c0 * LDP + k0 + t + 4], bh[nf][1], bl[nf][1]);
            }
#pragma unroll
            for (int mf = 0; mf < 2; mf++)
#pragma unroll
                for (int nf = 0; nf < 4; nf++) {
                    mma8(acc[mf][nf], al[mf], bh[nf]);
                    mma8(acc[mf][nf], ah[mf], bl[nf]);
                    mma8(acc[mf][nf], ah[mf], bh[nf]);
                }
        }
        __syncthreads();
    }

#pragma unroll
    for (int mf = 0; mf < 2; mf++)
#pragma unroll
        for (int nf = 0; nf < 4; nf++) {
            int r0 = warpM * 32 + mf * 16 + g;
            int c0 = warpN * 32 + nf * 8 + 2 * t;
            float b0 = __ldg(bias + c0), b1 = __ldg(bias + c0 + 1);
            sD[r0 * LDD + c0]           = acc[mf][nf][0] + b0;
            sD[r0 * LDD + c0 + 1]       = acc[mf][nf][1] + b1;
            sD[(r0 + 8) * LDD + c0]     = acc[mf][nf][2] + b0;
            sD[(r0 + 8) * LDD + c0 + 1] = acc[mf][nf][3] + b1;
        }
    __syncthreads();

    {
        int row = tid >> 2, q = tid & 3;
        const float* dr = sD + row * LDD + q * 32;
        float sq = 0.f, h0 = 0.f;
#pragma unroll
        for (int c = 0; c < 32; c++) { float v = dr[c]; sq += v * v; }
        if (q == 0) { h0 = dr[0]; sq -= h0 * h0; }
        sq += __shfl_xor_sync(0xffffffffu, sq, 1);
        sq += __shfl_xor_sync(0xffffffffu, sq, 2);
        if (q == 0) {
            float sEff = fminf(expf(logs[0]), 10.0f);
            sq = fmaxf(sq, EPSV);
            float tme = sEff / (1.f + expf(-h0)) + 1.5f;
            float sc = sqrtf(fmaxf((tme * tme - 1.0f) / sq, EPSV));
            rowT[row] = tme;
            rowS[row] = sc;
        }
    }
    __syncthreads();

    {
        int row = tid >> 2, q = tid & 3;
        int gr = rowBase + row;
        if (gr < NN) {
            float tme = rowT[row], sc = rowS[row];
            const float* dr = sD + row * LDD + q * 32;
            float* op = out + (size_t)gr * DD + q * 32;
#pragma unroll
            for (int c4 = 0; c4 < 8; c4++) {
                float4 v = *(const float4*)(dr + c4 * 4);
                v.x *= sc; v.y *= sc; v.z *= sc; v.w *= sc;
                if (q == 0 && c4 == 0) v.x = tme;
                *(float4*)(op + c4 * 4) = v;
            }
        }
    }
}

// ---------------------------------------------------------------------------
// Gather aggregation: one warp per node. Lane-parallel index staging:
// lane l loads pair[s + chunk + l] in one coalesced access, then the inner
// loop broadcasts (col, w) via shfl. All row-loads are independent -> high MLP.
// MODE 0: normalize + relu. MODE 1: normalize + class logits.
// ---------------------------------------------------------------------------
template<int MODE>
__global__ __launch_bounds__(256) void agg_gather(
    const float* __restrict__ Y,
    const int* __restrict__ offs, const int* __restrict__ deg,
    const int2* __restrict__ pair,
    const float* __restrict__ cls, const float* __restrict__ cbias,
    float* __restrict__ out) {

    __shared__ float clsS[MODE ? NCLS * DD : 1];
    __shared__ float cbS[MODE ? NCLS : 1];
    if (MODE) {
        for (int i = threadIdx.x; i < NCLS * DD; i += blockDim.x) clsS[i] = cls[i];
        if (threadIdx.x < NCLS) cbS[threadIdx.x] = cbias[threadIdx.x];
        __syncthreads();
    }

    int lane = threadIdx.x & 31;
    int node = (blockIdx.x * blockDim.x + threadIdx.x) >> 5;
    if (node >= NN) return;

    int s = offs[node];
    int n = deg[node];
    const float4* Yv = (const float4*)Y;
    float4 acc = make_float4(0.f, 0.f, 0.f, 0.f);

    for (int base = 0; base < n; base += 32) {
        int m = n - base; if (m > 32) m = 32;
        int2 pr = make_int2(0, 0);
        if (lane < m) pr = pair[s + base + lane];
#pragma unroll 4
        for (int i = 0; i < m; i++) {
            int   col = __shfl_sync(0xffffffffu, pr.x, i);
            float w   = __int_as_float(__shfl_sync(0xffffffffu, pr.y, i));
            float4 v = Yv[(size_t)col * 32 + lane];
            acc.x += w * v.x; acc.y += w * v.y;
            acc.z += w * v.z; acc.w += w * v.w;
        }
    }

    float ss = acc.x * acc.x + acc.y * acc.y + acc.z * acc.z + acc.w * acc.w;
    ss = warpSum(ss);
    float s0 = __shfl_sync(0xffffffffu, acc.x, 0);
    float neg = 2.f * s0 * s0 - ss;
    float inv = rsqrtf(fmaxf(fabsf(neg), EPSV));

    if (MODE == 0) {
        float4 v;
        v.x = fmaxf(acc.x * inv, 0.f);
        v.y = fmaxf(acc.y * inv, 0.f);
        v.z = fmaxf(acc.z * inv, 0.f);
        v.w = fmaxf(acc.w * inv, 0.f);
        *(float4*)(out + (size_t)node * DD + lane * 4) = v;
    } else {
        float x0 = s0 * inv;
        float4 v;
        v.x = acc.x * inv; v.y = acc.y * inv; v.z = acc.z * inv; v.w = acc.w * inv;
#pragma unroll 4
        for (int c = 0; c < NCLS; c++) {
            const float4 w = *(const float4*)(clsS + c * DD + lane * 4);
            float d = v.x * w.x + v.y * w.y + v.z * w.z + v.w * w.w;
            d = warpSum(d);
            if (lane == 0) {
                float w0 = clsS[c * DD];
                out[(size_t)node * NCLS + c] = 2.0f + 2.0f * (d - 2.f * x0 * w0) + cbS[c];
            }
        }
    }
}

// ---------------------------------------------------------------------------
extern "C" void kernel_launch(void* const* d_in, const int* in_sizes, int n_in,
                              void* d_out, int out_size) {
    const float* node_feat = (const float*)d_in[0];
    const float* W1   = (const float*)d_in[1];
    const float* b1   = (const float*)d_in[2];
    const float* s1   = (const float*)d_in[3];
    const float* W2   = (const float*)d_in[4];
    const float* b2   = (const float*)d_in[5];
    const float* s2   = (const float*)d_in[6];
    const float* cls  = (const float*)d_in[7];
    const float* cbias= (const float*)d_in[8];
    const float* ew   = (const float*)d_in[9];
    const int*   er   = (const int*)d_in[10];
    const int*   ec   = (const int*)d_in[11];
    float* out = (float*)d_out;

    float *A, *B;
    int *deg, *offs, *cursor;
    int2 *pair;
    cudaGetSymbolAddress((void**)&A, g_A);
    cudaGetSymbolAddress((void**)&B, g_B);
    cudaGetSymbolAddress((void**)&deg, g_deg);
    cudaGetSymbolAddress((void**)&offs, g_offs);
    cudaGetSymbolAddress((void**)&cursor, g_cursor);
    cudaGetSymbolAddress((void**)&pair, g_pair);

    const int WARPS_BLOCKS = (NN + 7) / 8;         // 6250
    const int GEMM_BLOCKS  = (NN + GBM - 1) / GBM; // 782
    const int GEMM_SMEM = (GBM * LDP + 128 * LDP + 2 * GBM) * 4;

    cudaFuncSetAttribute(gemm_tc, cudaFuncAttributeMaxDynamicSharedMemorySize,
                         GEMM_SMEM);

    // Edge binning (shared by both aggregations)
    cudaMemsetAsync(deg, 0, NN * sizeof(int));
    count_kernel<<<1024, 256>>>(er, deg);
    scan_kernel<<<1, 1024>>>(deg, offs, cursor);
    scatter_kernel<<<1024, 256>>>(er, ec, ew, cursor, pair);

    // Pipeline
    expmap_kernel<<<WARPS_BLOCKS, 256>>>(node_feat, A);
    gemm_tc<<<GEMM_BLOCKS, 256, GEMM_SMEM>>>(A, W1, b1, s1, B);
    agg_gather<0><<<WARPS_BLOCKS, 256>>>(B, offs, deg, pair, nullptr, nullptr, A);
    gemm_tc<<<GEMM_BLOCKS, 256, GEMM_SMEM>>>(A, W2, b2, s2, B);
    agg_gather<1><<<WARPS_BLOCKS, 256>>>(B, offs, deg, pair, cls, cbias, out);
}

// round 5
// speedup vs baseline: 1.1097x; 1.1097x over previous
#include <cuda_runtime.h>
#include <math.h>

#define NN   50000
#define EE   800000
#define DIN  127
#define DD   128
#define NCLS 40
#define EPSV 1e-8f

#define GBM  64      // gemm block rows
#define LDP  68      // smem panel leading dim (floats)
#define LDD  132     // D staging leading dim

// Scratch (__device__ globals: allocation-free rule)
__device__ float g_A[NN * DD];
__device__ float g_B[NN * DD];
__device__ int   g_deg[NN];
__device__ int   g_offs[NN];
__device__ int   g_cursor[NN];
__device__ int2  g_pair[EE];

__device__ __forceinline__ float warpSum(float v) {
#pragma unroll
    for (int o = 16; o; o >>= 1) v += __shfl_xor_sync(0xffffffffu, v, o);
    return v;
}

__device__ __forceinline__ void split_tf32(float x, unsigned& hi, unsigned& lo) {
    unsigned h;
    asm("cvt.rna.tf32.f32 %0, %1;" : "=r"(h) : "f"(x));
    float r = x - __uint_as_float(h);
    unsigned l;
    asm("cvt.rna.tf32.f32 %0, %1;" : "=r"(l) : "f"(r));
    hi = h; lo = l;
}

__device__ __forceinline__ void mma8(float* d, const unsigned* a, const unsigned* b) {
    asm volatile(
        "mma.sync.aligned.m16n8k8.row.col.f32.tf32.tf32.f32 "
        "{%0,%1,%2,%3}, {%4,%5,%6,%7}, {%8,%9}, {%0,%1,%2,%3};"
        : "+f"(d[0]), "+f"(d[1]), "+f"(d[2]), "+f"(d[3])
        : "r"(a[0]), "r"(a[1]), "r"(a[2]), "r"(a[3]), "r"(b[0]), "r"(b[1]));
}

// ---------------------------------------------------------------------------
// Edge binning
// ---------------------------------------------------------------------------
__global__ void count_kernel(const int* __restrict__ er, int* __restrict__ deg) {
    int i = blockIdx.x * blockDim.x + threadIdx.x;
    int stride = gridDim.x * blockDim.x;
    for (int e = i; e < EE; e += stride) atomicAdd(&deg[er[e]], 1);
}

__global__ void scan_kernel(const int* __restrict__ deg, int* __restrict__ offs,
                            int* __restrict__ cursor) {
    __shared__ int sums[1024];
    const int CH = (NN + 1023) / 1024;
    int t = threadIdx.x;
    int base = t * CH;
    int s = 0;
    for (int i = 0; i < CH; i++) {
        int idx = base + i;
        if (idx < NN) s += deg[idx];
    }
    sums[t] = s;
    __syncthreads();
    for (int o = 1; o < 1024; o <<= 1) {
        int v = (t >= o) ? sums[t - o] : 0;
        __syncthreads();
        sums[t] += v;
        __syncthreads();
    }
    int run = (t == 0) ? 0 : sums[t - 1];
    for (int i = 0; i < CH; i++) {
        int idx = base + i;
        if (idx < NN) {
            offs[idx] = run;
            cursor[idx] = run;
            run += deg[idx];
        }
    }
}

__global__ void scatter_kernel(const int* __restrict__ er, const int* __restrict__ ec,
                               const float* __restrict__ ew,
                               int* __restrict__ cursor, int2* __restrict__ pair) {
    int i = blockIdx.x * blockDim.x + threadIdx.x;
    int stride = gridDim.x * blockDim.x;
    for (int e = i; e < EE; e += stride) {
        int r = er[e];
        int pos = atomicAdd(&cursor[r], 1);
        pair[pos] = make_int2(ec[e], __float_as_int(ew[e]));
    }
}

// ---------------------------------------------------------------------------
// expmap0: one warp per node
// ---------------------------------------------------------------------------
__global__ void expmap_kernel(const float* __restrict__ nf, float* __restrict__ out) {
    int lane = threadIdx.x & 31;
    int warp = (blockIdx.x * blockDim.x + threadIdx.x) >> 5;
    if (warp >= NN) return;
    const float* u = nf + (size_t)warp * DIN;
    float v[4];
    float ss = 0.f;
#pragma unroll
    for (int i = 0; i < 4; i++) {
        int j = lane * 4 + i;
        v[i] = (j < DIN) ? u[j] : 0.f;
        ss += v[i] * v[i];
    }
    ss = warpSum(ss);
    float nrm = fmaxf(sqrtf(ss), EPSV);
    float f = sinhf(nrm) / nrm;
    float* o = out + (size_t)warp * DD;
    if (lane == 0) o[0] = coshf(nrm);
#pragma unroll
    for (int i = 0; i < 4; i++) {
        int j = lane * 4 + i;
        if (j < DIN) o[1 + j] = f * v[i];
    }
}

// ---------------------------------------------------------------------------
// GEMM via 3xTF32 mma.sync: H = X @ W^T + b, Lorentz epilogue.
// ---------------------------------------------------------------------------
__global__ void __launch_bounds__(256, 2) gemm_tc(
    const float* __restrict__ X, const float* __restrict__ W,
    const float* __restrict__ bias, const float* __restrict__ logs,
    float* __restrict__ out) {
    extern __shared__ float sm[];
    float* sX = sm;
    float* sW = sm + GBM * LDP;
    float* sD = sm;
    float* rowT = sm + GBM * LDP + 128 * LDP;
    float* rowS = rowT + GBM;

    int tid = threadIdx.x;
    int lane = tid & 31, wid = tid >> 5;
    int g = lane >> 2, t = lane & 3;
    int warpM = wid & 1, warpN = wid >> 1;
    int rowBase = blockIdx.x * GBM;

    float acc[2][4][4];
#pragma unroll
    for (int a = 0; a < 2; a++)
#pragma unroll
        for (int b = 0; b < 4; b++)
#pragma unroll
            for (int c = 0; c < 4; c++) acc[a][b][c] = 0.f;

    for (int kb = 0; kb < DD; kb += 64) {
#pragma unroll
        for (int i = 0; i < 4; i++) {
            int idx = tid + 256 * i;
            int r = idx >> 4, c4 = idx & 15;
            int gr = rowBase + r;
            float4 v = make_float4(0.f, 0.f, 0.f, 0.f);
            if (gr < NN) v = *(const float4*)(X + (size_t)gr * DD + kb + c4 * 4);
            *(float4*)(sX + r * LDP + c4 * 4) = v;
        }
#pragma unroll
        for (int i = 0; i < 8; i++) {
            int idx = tid + 256 * i;
            int r = idx >> 4, c4 = idx & 15;
            float4 v = *(const float4*)(W + (size_t)r * DD + kb + c4 * 4);
            *(float4*)(sW + r * LDP + c4 * 4) = v;
        }
        __syncthreads();

#pragma unroll
        for (int ks = 0; ks < 8; ks++) {
            int k0 = ks * 8;
            unsigned ah[2][4], al[2][4], bh[4][2], bl[4][2];
#pragma unroll
            for (int mf = 0; mf < 2; mf++) {
                int r0 = warpM * 32 + mf * 16 + g;
                split_tf32(sX[r0 * LDP + k0 + t],           ah[mf][0], al[mf][0]);
                split_tf32(sX[(r0 + 8) * LDP + k0 + t],     ah[mf][1], al[mf][1]);
                split_tf32(sX[r0 * LDP + k0 + t + 4],       ah[mf][2], al[mf][2]);
                split_tf32(sX[(r0 + 8) * LDP + k0 + t + 4], ah[mf][3], al[mf][3]);
            }
#pragma unroll
            for (int nf = 0; nf < 4; nf++) {
                int c0 = warpN * 32 + nf * 8 + g;
                split_tf32(sW[c0 * LDP + k0 + t],     bh[nf][0], bl[nf][0]);
                split_tf32(sW[c0 * LDP + k0 + t + 4], bh[nf][1], bl[nf][1]);
            }
#pragma unroll
            for (int mf = 0; mf < 2; mf++)
#pragma unroll
                for (int nf = 0; nf < 4; nf++) {
                    mma8(acc[mf][nf], al[mf], bh[nf]);
                    mma8(acc[mf][nf], ah[mf], bl[nf]);
                    mma8(acc[mf][nf], ah[mf], bh[nf]);
                }
        }
        __syncthreads();
    }

#pragma unroll
    for (int mf = 0; mf < 2; mf++)
#pragma unroll
        for (int nf = 0; nf < 4; nf++) {
            int r0 = warpM * 32 + mf * 16 + g;
            int c0 = warpN * 32 + nf * 8 + 2 * t;
            float b0 = __ldg(bias + c0), b1 = __ldg(bias + c0 + 1);
            sD[r0 * LDD + c0]           = acc[mf][nf][0] + b0;
            sD[r0 * LDD + c0 + 1]       = acc[mf][nf][1] + b1;
            sD[(r0 + 8) * LDD + c0]     = acc[mf][nf][2] + b0;
            sD[(r0 + 8) * LDD + c0 + 1] = acc[mf][nf][3] + b1;
        }
    __syncthreads();

    {
        int row = tid >> 2, q = tid & 3;
        const float* dr = sD + row * LDD + q * 32;
        float sq = 0.f, h0 = 0.f;
#pragma unroll
        for (int c = 0; c < 32; c++) { float v = dr[c]; sq += v * v; }
        if (q == 0) { h0 = dr[0]; sq -= h0 * h0; }
        sq += __shfl_xor_sync(0xffffffffu, sq, 1);
        sq += __shfl_xor_sync(0xffffffffu, sq, 2);
        if (q == 0) {
            float sEff = fminf(expf(logs[0]), 10.0f);
            sq = fmaxf(sq, EPSV);
            float tme = sEff / (1.f + expf(-h0)) + 1.5f;
            float sc = sqrtf(fmaxf((tme * tme - 1.0f) / sq, EPSV));
            rowT[row] = tme;
            rowS[row] = sc;
        }
    }
    __syncthreads();

    {
        int row = tid >> 2, q = tid & 3;
        int gr = rowBase + row;
        if (gr < NN) {
            float tme = rowT[row], sc = rowS[row];
            const float* dr = sD + row * LDD + q * 32;
            float* op = out + (size_t)gr * DD + q * 32;
#pragma unroll
            for (int c4 = 0; c4 < 8; c4++) {
                float4 v = *(const float4*)(dr + c4 * 4);
                v.x *= sc; v.y *= sc; v.z *= sc; v.w *= sc;
                if (q == 0 && c4 == 0) v.x = tme;
                *(float4*)(op + c4 * 4) = v;
            }
        }
    }
}

// ---------------------------------------------------------------------------
// Gather aggregation: one warp per node. Lane-parallel index staging + inner
// loop padded to multiples of 8 and fully unrolled: 8 independent row-LDGs
// in flight per batch (inactive slots read row 0 with weight 0).
// MODE 0: normalize + relu. MODE 1: normalize + class logits.
// ---------------------------------------------------------------------------
template<int MODE>
__global__ __launch_bounds__(256) void agg_gather(
    const float* __restrict__ Y,
    const int* __restrict__ offs, const int* __restrict__ deg,
    const int2* __restrict__ pair,
    const float* __restrict__ cls, const float* __restrict__ cbias,
    float* __restrict__ out) {

    __shared__ float clsS[MODE ? NCLS * DD : 1];
    __shared__ float cbS[MODE ? NCLS : 1];
    if (MODE) {
        for (int i = threadIdx.x; i < NCLS * DD; i += blockDim.x) clsS[i] = cls[i];
        if (threadIdx.x < NCLS) cbS[threadIdx.x] = cbias[threadIdx.x];
        __syncthreads();
    }

    int lane = threadIdx.x & 31;
    int node = (blockIdx.x * blockDim.x + threadIdx.x) >> 5;
    if (node >= NN) return;

    int s = offs[node];
    int n = deg[node];
    const float4* Yv = (const float4*)Y;
    float4 acc = make_float4(0.f, 0.f, 0.f, 0.f);

    for (int base = 0; base < n; base += 32) {
        int m = n - base; if (m > 32) m = 32;
        int2 pr = make_int2(0, 0);            // inactive: row 0, weight 0
        if (lane < m) pr = pair[s + base + lane];
        int mp = (m + 7) & ~7;                // pad to multiple of 8
        for (int i0 = 0; i0 < mp; i0 += 8) {
            float4 v[8]; float w[8];
#pragma unroll
            for (int k = 0; k < 8; k++) {
                int   col = __shfl_sync(0xffffffffu, pr.x, i0 + k);
                w[k] = __int_as_float(__shfl_sync(0xffffffffu, pr.y, i0 + k));
                v[k] = Yv[(size_t)col * 32 + lane];
            }
#pragma unroll
            for (int k = 0; k < 8; k++) {
                acc.x += w[k] * v[k].x; acc.y += w[k] * v[k].y;
                acc.z += w[k] * v[k].z; acc.w += w[k] * v[k].w;
            }
        }
    }

    float ss = acc.x * acc.x + acc.y * acc.y + acc.z * acc.z + acc.w * acc.w;
    ss = warpSum(ss);
    float s0 = __shfl_sync(0xffffffffu, acc.x, 0);
    float neg = 2.f * s0 * s0 - ss;
    float inv = rsqrtf(fmaxf(fabsf(neg), EPSV));

    if (MODE == 0) {
        float4 v;
        v.x = fmaxf(acc.x * inv, 0.f);
        v.y = fmaxf(acc.y * inv, 0.f);
        v.z = fmaxf(acc.z * inv, 0.f);
        v.w = fmaxf(acc.w * inv, 0.f);
        *(float4*)(out + (size_t)node * DD + lane * 4) = v;
    } else {
        float x0 = s0 * inv;
        float4 v;
        v.x = acc.x * inv; v.y = acc.y * inv; v.z = acc.z * inv; v.w = acc.w * inv;
#pragma unroll 4
        for (int c = 0; c < NCLS; c++) {
            const float4 w = *(const float4*)(clsS + c * DD + lane * 4);
            float d = v.x * w.x + v.y * w.y + v.z * w.z + v.w * w.w;
            d = warpSum(d);
            if (lane == 0) {
                float w0 = clsS[c * DD];
                out[(size_t)node * NCLS + c] = 2.0f + 2.0f * (d - 2.f * x0 * w0) + cbS[c];
            }
        }
    }
}

// ---------------------------------------------------------------------------
extern "C" void kernel_launch(void* const* d_in, const int* in_sizes, int n_in,
                              void* d_out, int out_size) {
    const float* node_feat = (const float*)d_in[0];
    const float* W1   = (const float*)d_in[1];
    const float* b1   = (const float*)d_in[2];
    const float* s1   = (const float*)d_in[3];
    const float* W2   = (const float*)d_in[4];
    const float* b2   = (const float*)d_in[5];
    const float* s2   = (const float*)d_in[6];
    const float* cls  = (const float*)d_in[7];
    const float* cbias= (const float*)d_in[8];
    const float* ew   = (const float*)d_in[9];
    const int*   er   = (const int*)d_in[10];
    const int*   ec   = (const int*)d_in[11];
    float* out = (float*)d_out;

    float *A, *B;
    int *deg, *offs, *cursor;
    int2 *pair;
    cudaGetSymbolAddress((void**)&A, g_A);
    cudaGetSymbolAddress((void**)&B, g_B);
    cudaGetSymbolAddress((void**)&deg, g_deg);
    cudaGetSymbolAddress((void**)&offs, g_offs);
    cudaGetSymbolAddress((void**)&cursor, g_cursor);
    cudaGetSymbolAddress((void**)&pair, g_pair);

    const int WARPS_BLOCKS = (NN + 7) / 8;         // 6250
    const int GEMM_BLOCKS  = (NN + GBM - 1) / GBM; // 782
    const int GEMM_SMEM = (GBM * LDP + 128 * LDP + 2 * GBM) * 4;

    cudaFuncSetAttribute(gemm_tc, cudaFuncAttributeMaxDynamicSharedMemorySize,
                         GEMM_SMEM);

    // Side stream + events for fork/join inside graph capture (created once).
    static cudaStream_t s2s = nullptr;
    static cudaEvent_t evFork = nullptr, evJoin = nullptr;
    if (!s2s) {
        cudaStreamCreateWithFlags(&s2s, cudaStreamNonBlocking);
        cudaEventCreateWithFlags(&evFork, cudaEventDisableTiming);
        cudaEventCreateWithFlags(&evJoin, cudaEventDisableTiming);
    }

    // Fork: binning chain on side stream, concurrent with expmap + gemm1.
    cudaEventRecord(evFork, 0);
    cudaStreamWaitEvent(s2s, evFork, 0);
    cudaMemsetAsync(deg, 0, NN * sizeof(int), s2s);
    count_kernel<<<1024, 256, 0, s2s>>>(er, deg);
    scan_kernel<<<1, 1024, 0, s2s>>>(deg, offs, cursor);
    scatter_kernel<<<1024, 256, 0, s2s>>>(er, ec, ew, cursor, pair);
    cudaEventRecord(evJoin, s2s);

    // Main stream
    expmap_kernel<<<WARPS_BLOCKS, 256>>>(node_feat, A);
    gemm_tc<<<GEMM_BLOCKS, 256, GEMM_SMEM>>>(A, W1, b1, s1, B);
    cudaStreamWaitEvent(0, evJoin, 0);   // join before first aggregation
    agg_gather<0><<<WARPS_BLOCKS, 256>>>(B, offs, deg, pair, nullptr, nullptr, A);
    gemm_tc<<<GEMM_BLOCKS, 256, GEMM_SMEM>>>(A, W2, b2, s2, B);
    agg_gather<1><<<WARPS_BLOCKS, 256>>>(B, offs, deg, pair, cls, cbias, out);
}